// round 3
// baseline (speedup 1.0000x reference)
#include <cuda_runtime.h>
#include <cuda_bf16.h>
#include <math.h>
#include <stdint.h>

#define BATCH 2
#define NPTS 8192
#define NB (BATCH * NPTS)       // 16384
#define KNN 24
#define DM 128
#define RROWS (NB * KNN)        // 393216
#define RELEMS ((size_t)RROWS * DM)

// ---------------- static device scratch ----------------
__device__ float  g_x[(size_t)NB * DM];          // x = features@fc1+b (fp32)
__device__ float4 g_xyzw[NB];                    // xyz + sqnorm packed
__device__ int    g_idx[(size_t)NB * KNN];
__device__ unsigned short g_pe_hi[(size_t)RROWS * 64];
__device__ unsigned short g_pe_lo[(size_t)RROWS * 64];
__device__ unsigned short g_h_hi[RELEMS];        // h1 / h2 split bf16
__device__ unsigned short g_h_lo[RELEMS];
__device__ unsigned short g_AI_hi[RELEMS];       // attn_in split bf16
__device__ unsigned short g_AI_lo[RELEMS];
__device__ float  g_P[RELEMS];                   // pos_enc fp32
__device__ float  g_res0[(size_t)NB * DM];
__device__ unsigned short g_Whi[3 * DM * DM + DM * 64];  // W^T split (d2,g1,g2,[d1 pad64])
__device__ unsigned short g_Wlo[3 * DM * DM + DM * 64];

// ---------------- helpers ----------------
__device__ __forceinline__ uint32_t smem_u32(const void* p) {
    uint32_t a;
    asm("{ .reg .u64 t; cvta.to.shared.u64 t, %1; cvt.u32.u64 %0, t; }" : "=r"(a) : "l"(p));
    return a;
}
__device__ __forceinline__ void ldsm4(uint32_t* r, uint32_t a) {
    asm volatile("ldmatrix.sync.aligned.m8n8.x4.shared.b16 {%0,%1,%2,%3}, [%4];"
                 : "=r"(r[0]), "=r"(r[1]), "=r"(r[2]), "=r"(r[3]) : "r"(a));
}
__device__ __forceinline__ void mma_bf16(float* d, const uint32_t* a, const uint32_t* b) {
    asm volatile(
        "mma.sync.aligned.m16n8k16.row.col.f32.bf16.bf16.f32 "
        "{%0,%1,%2,%3}, {%4,%5,%6,%7}, {%8,%9}, {%0,%1,%2,%3};"
        : "+f"(d[0]), "+f"(d[1]), "+f"(d[2]), "+f"(d[3])
        : "r"(a[0]), "r"(a[1]), "r"(a[2]), "r"(a[3]), "r"(b[0]), "r"(b[1]));
}
__device__ __forceinline__ void split2(float v, unsigned short& h, unsigned short& l) {
    __nv_bfloat16 bh = __float2bfloat16(v);
    float r = v - __bfloat162float(bh);
    __nv_bfloat16 bl = __float2bfloat16(r);
    h = *reinterpret_cast<unsigned short*>(&bh);
    l = *reinterpret_cast<unsigned short*>(&bl);
}

// ---------------- weight prep: W^T split bf16 ----------------
__global__ void k_prep_w(const float* __restrict__ d2w, const float* __restrict__ g1w,
                         const float* __restrict__ g2w, const float* __restrict__ d1w) {
    int e = blockIdx.x * blockDim.x + threadIdx.x;
    if (e >= 3 * DM * DM + DM * 64) return;
    float v;
    if (e < 3 * DM * DM) {
        int m = e >> 14;
        int r = e & 16383;
        int n = r >> 7, k = r & 127;
        const float* W = (m == 0) ? d2w : (m == 1) ? g1w : g2w;
        v = W[k * DM + n];
    } else {
        int e2 = e - 3 * DM * DM;
        int n = e2 >> 6, k = e2 & 63;
        v = (k < 60) ? d1w[k * DM + n] : 0.0f;
    }
    unsigned short h, l;
    split2(v, h, l);
    g_Whi[e] = h;
    g_Wlo[e] = l;
}

// ---------------- x = features@fc1 + b, pack xyzw ----------------
__global__ void k_fc1(const float* __restrict__ feat, const float* __restrict__ xyz,
                      const float* __restrict__ w, const float* __restrict__ b) {
    __shared__ float sf[8][32];
    int n0 = blockIdx.x * 8;
    int t = threadIdx.x;
    for (int e = t; e < 8 * 32; e += 128)
        sf[e / 32][e % 32] = feat[(size_t)(n0 + e / 32) * 32 + (e % 32)];
    __syncthreads();
    float acc[8];
#pragma unroll
    for (int r = 0; r < 8; ++r) acc[r] = 0.0f;
    int d = t;
    for (int c = 0; c < 32; ++c) {
        float wv = w[c * DM + d];
#pragma unroll
        for (int r = 0; r < 8; ++r) acc[r] = fmaf(sf[r][c], wv, acc[r]);
    }
    float bv = b[d];
#pragma unroll
    for (int r = 0; r < 8; ++r)
        g_x[(size_t)(n0 + r) * DM + d] = acc[r] + bv;
    if (t < 8) {
        int n = n0 + t;
        float x0 = xyz[(size_t)n * 3 + 0];
        float x1 = xyz[(size_t)n * 3 + 1];
        float x2 = xyz[(size_t)n * 3 + 2];
        float sq = __fadd_rn(__fadd_rn(__fmul_rn(x0, x0), __fmul_rn(x1, x1)), __fmul_rn(x2, x2));
        g_xyzw[n] = make_float4(x0, x1, x2, sq);
    }
}

// ---------------- KNN: 4 threads per query + stable merge ----------------
__global__ void k_knn() {
    int t = threadIdx.x;                   // 128
    int ql = t & 31;
    int p = t >> 5;                        // partition 0..3
    int q = blockIdx.x * 32 + ql;
    int b = q >> 13;
    int base = b << 13;

    float4 qv = g_xyzw[q];
    float dist[KNN];
    int   nidx[KNN];
#pragma unroll
    for (int i = 0; i < KNN; ++i) { dist[i] = INFINITY; nidx[i] = 0x7fffffff; }

    const float4* cand = &g_xyzw[base + p * 2048];
#pragma unroll 4
    for (int i = 0; i < 2048; ++i) {
        float4 c = cand[i];
        float dot = __fadd_rn(__fadd_rn(__fmul_rn(qv.x, c.x), __fmul_rn(qv.y, c.y)),
                              __fmul_rn(qv.z, c.z));
        float dd = __fsub_rn(__fadd_rn(qv.w, c.w), __fmul_rn(2.0f, dot));
        if (dd < dist[KNN - 1]) {
            int j = KNN - 1;
            while (j > 0 && dist[j - 1] > dd) {
                dist[j] = dist[j - 1]; nidx[j] = nidx[j - 1]; --j;
            }
            dist[j] = dd; nidx[j] = p * 2048 + i;
        }
    }

    __shared__ float sd[128][KNN];
    __shared__ int   si[128][KNN];
#pragma unroll
    for (int k = 0; k < KNN; ++k) { sd[t][k] = dist[k]; si[t][k] = nidx[k]; }
    __syncthreads();

    if (p == 0) {
        int ptr[4] = {0, 0, 0, 0};
#pragma unroll
        for (int k = 0; k < KNN; ++k) {
            float bd = INFINITY; int bi = 0x7fffffff; int bp = 0;
#pragma unroll
            for (int pp = 0; pp < 4; ++pp) {
                int tp = pp * 32 + ql;
                float d = sd[tp][ptr[pp]];
                int   ii = si[tp][ptr[pp]];
                if (d < bd || (d == bd && ii < bi)) { bd = d; bi = ii; bp = pp; }
            }
            g_idx[(size_t)q * KNN + k] = bi;
            ptr[bp]++;
        }
    }
}

// ---------------- pe generation: sincos -> split bf16 [RROWS x 64] ----------------
__global__ void k_pe_gen() {
    int n0 = blockIdx.x * 8;          // 8 nodes per block
    int t = threadIdx.x;              // 256
    __shared__ float gk[192][3];

    if (t < 192) {
        int n = n0 + t / 24;
        int base = (n >> 13) << 13;
        int id = g_idx[(size_t)n * KNN + (t % 24)];
        float4 q = g_xyzw[n];
        float4 c = g_xyzw[base + id];
        gk[t][0] = q.x - c.x; gk[t][1] = q.y - c.y; gk[t][2] = q.z - c.z;
    }
    __syncthreads();

    const float LOGC = -1.3287712379549449f;  // -log2(10000)/10
    for (int e = t; e < 192 * 64; e += 256) {
        int rl = e >> 6, j = e & 63;
        unsigned short h = 0, l = 0;
        if (j < 60) {
            int c = j / 20, rr = j % 20, m = rr % 10;
            float om = exp2f((float)m * LOGC);
            float ph = gk[rl][c] * om;
            float val = (rr < 10) ? __sinf(ph) : __cosf(ph);
            split2(val, h, l);
        }
        size_t off = ((size_t)n0 * 24 + rl) * 64 + j;
        g_pe_hi[off] = h;
        g_pe_lo[off] = l;
    }
}

// ---------------- HMMA split-bf16 GEMM: C = act(A@W + b), N=128, K = KE ----------------
// modes: 0 = pos_enc(fp32)+attn_in(split) ; 1 = relu->split g_h ; 2 = fp32 -> outp
template <int KE>
__global__ void __launch_bounds__(256, 1)
k_mma(const unsigned short* __restrict__ Ahi, const unsigned short* __restrict__ Alo,
      const unsigned short* __restrict__ Bhi, const unsigned short* __restrict__ Blo,
      const float* __restrict__ bias, float* __restrict__ outp, int mode) {
    constexpr int KB = KE * 2;        // bytes per smem row
    constexpr int CH = KB / 16;       // 16B chunks per row
    constexpr int KSTEPS = KE / 16;
    constexpr int MAT = 128 * KB;     // bytes per tile

    extern __shared__ char smem[];
    char* sAhi = smem;
    char* sAlo = smem + MAT;
    char* sBhi = smem + 2 * MAT;
    char* sBlo = smem + 3 * MAT;
    float* stage = reinterpret_cast<float*>(smem);   // reused post-MMA, stride 132

    int tid = threadIdx.x;
    int wid = tid >> 5, lane = tid & 31;
    int r0 = blockIdx.x * 128;

    // ---- load tiles (XOR-swizzled) ----
    for (int e = tid; e < 128 * CH; e += 256) {
        int row = e / CH;
        int c = e % CH;
        uint32_t so = (uint32_t)(row * KB + ((c ^ (row & 7)) << 4));
        size_t ga = (size_t)(r0 + row) * KE + c * 8;
        size_t gb = (size_t)row * KE + c * 8;
        *reinterpret_cast<uint4*>(sAhi + so) = *reinterpret_cast<const uint4*>(Ahi + ga);
        *reinterpret_cast<uint4*>(sAlo + so) = *reinterpret_cast<const uint4*>(Alo + ga);
        *reinterpret_cast<uint4*>(sBhi + so) = *reinterpret_cast<const uint4*>(Bhi + gb);
        *reinterpret_cast<uint4*>(sBlo + so) = *reinterpret_cast<const uint4*>(Blo + gb);
    }
    __syncthreads();

    int wm = (wid & 3) * 32;     // warp row base
    int wn = (wid >> 2) * 64;    // warp col base

    float acc[2][8][4];
#pragma unroll
    for (int i = 0; i < 2; ++i)
#pragma unroll
        for (int j = 0; j < 8; ++j)
#pragma unroll
            for (int q = 0; q < 4; ++q) acc[i][j][q] = 0.0f;

    uint32_t base_u = smem_u32(smem);
    uint32_t offA[3] = {0u, 0u, (uint32_t)MAT};
    uint32_t offB[3] = {(uint32_t)(2 * MAT), (uint32_t)(3 * MAT), (uint32_t)(2 * MAT)};

#pragma unroll
    for (int pass = 0; pass < 3; ++pass) {
        uint32_t sA = base_u + offA[pass];
        uint32_t sB = base_u + offB[pass];
#pragma unroll
        for (int ks = 0; ks < KSTEPS; ++ks) {
            int c0 = ks * 2;
            uint32_t a[2][4];
#pragma unroll
            for (int mt = 0; mt < 2; ++mt) {
                int r = wm + mt * 16 + (lane & 15);
                int c = c0 + (lane >> 4);
                ldsm4(a[mt], sA + r * KB + ((c ^ (r & 7)) << 4));
            }
            uint32_t bfr[8][2];
#pragma unroll
            for (int np = 0; np < 4; ++np) {
                int r = wn + np * 16 + ((lane >> 1) & 8) + (lane & 7);
                int c = c0 + ((lane >> 3) & 1);
                uint32_t tm[4];
                ldsm4(tm, sB + r * KB + ((c ^ (r & 7)) << 4));
                bfr[np * 2][0] = tm[0]; bfr[np * 2][1] = tm[1];
                bfr[np * 2 + 1][0] = tm[2]; bfr[np * 2 + 1][1] = tm[3];
            }
#pragma unroll
            for (int mt = 0; mt < 2; ++mt)
#pragma unroll
                for (int nt = 0; nt < 8; ++nt)
                    mma_bf16(acc[mt][nt], a[mt], bfr[nt]);
        }
    }

    __syncthreads();   // tiles dead; reuse as stage

    // ---- stage accumulators (fp32, stride 132) ----
#pragma unroll
    for (int mt = 0; mt < 2; ++mt)
#pragma unroll
        for (int nt = 0; nt < 8; ++nt) {
            int r = wm + mt * 16 + (lane >> 2);
            int cc = wn + nt * 8 + (lane & 3) * 2;
            *reinterpret_cast<float2*>(stage + r * 132 + cc) =
                make_float2(acc[mt][nt][0], acc[mt][nt][1]);
            *reinterpret_cast<float2*>(stage + (r + 8) * 132 + cc) =
                make_float2(acc[mt][nt][2], acc[mt][nt][3]);
        }
    __syncthreads();

    // ---- epilogue: warp-per-row, fully coalesced ----
    int col = lane * 4;
    float4 bv = *reinterpret_cast<const float4*>(bias + col);
#pragma unroll 1
    for (int it = 0; it < 16; ++it) {
        int row = wid + it * 8;
        int R = r0 + row;
        float4 v = *reinterpret_cast<const float4*>(stage + row * 132 + col);
        v.x += bv.x; v.y += bv.y; v.z += bv.z; v.w += bv.w;
        size_t off = (size_t)R * DM + col;
        if (mode == 2) {
            *reinterpret_cast<float4*>(outp + off) = v;
        } else if (mode == 1) {
            float vv[4] = {fmaxf(v.x, 0.f), fmaxf(v.y, 0.f), fmaxf(v.z, 0.f), fmaxf(v.w, 0.f)};
            unsigned short hs[4], ls[4];
#pragma unroll
            for (int j = 0; j < 4; ++j) split2(vv[j], hs[j], ls[j]);
            uint2 H, L;
            H.x = (uint32_t)hs[0] | ((uint32_t)hs[1] << 16);
            H.y = (uint32_t)hs[2] | ((uint32_t)hs[3] << 16);
            L.x = (uint32_t)ls[0] | ((uint32_t)ls[1] << 16);
            L.y = (uint32_t)ls[2] | ((uint32_t)ls[3] << 16);
            *reinterpret_cast<uint2*>(g_h_hi + off) = H;
            *reinterpret_cast<uint2*>(g_h_lo + off) = L;
        } else {
            int n = R / KNN;
            int kid = g_idx[R];
            int base = (n >> 13) << 13;
            float4 xn = *reinterpret_cast<const float4*>(g_x + (size_t)n * DM + col);
            float4 xk = *reinterpret_cast<const float4*>(g_x + (size_t)(base + kid) * DM + col);
            *reinterpret_cast<float4*>(g_P + off) = v;
            float ai[4] = {(xn.x - xk.x) + v.x, (xn.y - xk.y) + v.y,
                           (xn.z - xk.z) + v.z, (xn.w - xk.w) + v.w};
            unsigned short hs[4], ls[4];
#pragma unroll
            for (int j = 0; j < 4; ++j) split2(ai[j], hs[j], ls[j]);
            uint2 H, L;
            H.x = (uint32_t)hs[0] | ((uint32_t)hs[1] << 16);
            H.y = (uint32_t)hs[2] | ((uint32_t)hs[3] << 16);
            L.x = (uint32_t)ls[0] | ((uint32_t)ls[1] << 16);
            L.y = (uint32_t)ls[2] | ((uint32_t)ls[3] << 16);
            *reinterpret_cast<uint2*>(g_AI_hi + off) = H;
            *reinterpret_cast<uint2*>(g_AI_lo + off) = L;
        }
    }
}

// ---------------- softmax over K + weighted sum (pre in attn_out, in-place) ----------------
__global__ void k_softmax(float* __restrict__ attn_out) {
    int n = blockIdx.x;
    int d = threadIdx.x;
    int b = n >> 13;
    int base = b << 13;
    const float inv = 0.088388347648318447f;   // 1/sqrt(128)

    __shared__ int sidx[KNN];
    if (d < KNN) sidx[d] = g_idx[(size_t)n * KNN + d];
    __syncthreads();

    size_t roff = (size_t)n * KNN * DM + d;
    float a[KNN];
#pragma unroll
    for (int k = 0; k < KNN; ++k) a[k] = attn_out[roff + (size_t)k * DM] * inv;
    float m = a[0];
#pragma unroll
    for (int k = 1; k < KNN; ++k) m = fmaxf(m, a[k]);
    float s = 0.0f;
#pragma unroll
    for (int k = 0; k < KNN; ++k) { a[k] = expf(a[k] - m); s += a[k]; }
    float rs = 1.0f / s;

    float acc = 0.0f;
#pragma unroll
    for (int k = 0; k < KNN; ++k) {
        float at = a[k] * rs;
        size_t po = roff + (size_t)k * DM;
        attn_out[po] = at;
        float vv = g_x[(size_t)(base + sidx[k]) * DM + d] + g_P[po];
        acc = fmaf(at, vv, acc);
    }
    g_res0[(size_t)n * DM + d] = acc;
}

// ---------------- final: out = res0@fc2 + b + x ----------------
__global__ void k_final(const float* __restrict__ w, const float* __restrict__ b,
                        float* __restrict__ out_res) {
    __shared__ float s[8][DM];
    int n0 = blockIdx.x * 8;
    int t = threadIdx.x;
    for (int e = t; e < 8 * DM; e += 128)
        s[e >> 7][e & 127] = g_res0[(size_t)(n0 + (e >> 7)) * DM + (e & 127)];
    __syncthreads();
    float acc[8];
#pragma unroll
    for (int r = 0; r < 8; ++r) acc[r] = 0.0f;
    for (int c = 0; c < DM; ++c) {
        float wv = w[c * DM + t];
#pragma unroll
        for (int r = 0; r < 8; ++r) acc[r] = fmaf(s[r][c], wv, acc[r]);
    }
    float bv = b[t];
#pragma unroll
    for (int r = 0; r < 8; ++r)
        out_res[(size_t)(n0 + r) * DM + t] = (acc[r] + bv) + g_x[(size_t)(n0 + r) * DM + t];
}

// ---------------- launch ----------------
extern "C" void kernel_launch(void* const* d_in, const int* in_sizes, int n_in,
                              void* d_out, int out_size) {
    const float* features = (const float*)d_in[0];
    const float* xyz      = (const float*)d_in[1];
    const float* fc1_w    = (const float*)d_in[2];
    const float* fc1_b    = (const float*)d_in[3];
    const float* fc2_w    = (const float*)d_in[4];
    const float* fc2_b    = (const float*)d_in[5];
    const float* d1_w     = (const float*)d_in[6];
    const float* d1_b     = (const float*)d_in[7];
    const float* d2_w     = (const float*)d_in[8];
    const float* d2_b     = (const float*)d_in[9];
    const float* g1_w     = (const float*)d_in[10];
    const float* g1_b     = (const float*)d_in[11];
    const float* g2_w     = (const float*)d_in[12];
    const float* g2_b     = (const float*)d_in[13];

    float* out      = (float*)d_out;
    float* out_res  = out;
    float* out_attn = out + (size_t)NB * DM;

    const int SMEM128 = 128 * 256 * 4 + 1024;   // 4 tiles of 32KB (stage 67.6KB fits)
    const int SMEM64  = 128 * 132 * 4 + 1024;   // stage dominates (67.6KB)
    cudaFuncSetAttribute(k_mma<128>, cudaFuncAttributeMaxDynamicSharedMemorySize, SMEM128);
    cudaFuncSetAttribute(k_mma<64>,  cudaFuncAttributeMaxDynamicSharedMemorySize, SMEM64);

    unsigned short *pPEhi, *pPElo, *pHhi, *pHlo, *pAIhi, *pAIlo, *pWhi, *pWlo;
    cudaGetSymbolAddress((void**)&pPEhi, g_pe_hi);
    cudaGetSymbolAddress((void**)&pPElo, g_pe_lo);
    cudaGetSymbolAddress((void**)&pHhi,  g_h_hi);
    cudaGetSymbolAddress((void**)&pHlo,  g_h_lo);
    cudaGetSymbolAddress((void**)&pAIhi, g_AI_hi);
    cudaGetSymbolAddress((void**)&pAIlo, g_AI_lo);
    cudaGetSymbolAddress((void**)&pWhi,  g_Whi);
    cudaGetSymbolAddress((void**)&pWlo,  g_Wlo);

    const int W_D2 = 0, W_G1 = DM * DM, W_G2 = 2 * DM * DM, W_D1 = 3 * DM * DM;

    // 0. weight prep
    k_prep_w<<<(3 * DM * DM + DM * 64 + 255) / 256, 256>>>(d2_w, g1_w, g2_w, d1_w);
    // 1. fc1 + xyzw pack
    k_fc1<<<NB / 8, 128>>>(features, xyz, fc1_w, fc1_b);
    // 2. KNN
    k_knn<<<NB / 32, 128>>>();
    // 3. pe sincos -> split bf16
    k_pe_gen<<<NB / 8, 256>>>();
    // 4. h1 = relu(pe@d1 + b)   (K=64, mode 1)
    k_mma<64><<<RROWS / 128, 256, SMEM64>>>(pPEhi, pPElo, pWhi + W_D1, pWlo + W_D1, d1_b, nullptr, 1);
    // 5. pos_enc + attn_in = h1@d2 + b  (mode 0)
    k_mma<128><<<RROWS / 128, 256, SMEM128>>>(pHhi, pHlo, pWhi + W_D2, pWlo + W_D2, d2_b, nullptr, 0);
    // 6. h2 = relu(attn_in@g1 + b)  (mode 1)
    k_mma<128><<<RROWS / 128, 256, SMEM128>>>(pAIhi, pAIlo, pWhi + W_G1, pWlo + W_G1, g1_b, nullptr, 1);
    // 7. attn_pre = h2@g2 + b -> out_attn (mode 2)
    k_mma<128><<<RROWS / 128, 256, SMEM128>>>(pHhi, pHlo, pWhi + W_G2, pWlo + W_G2, g2_b, out_attn, 2);
    // 8. softmax (in place) + weighted sum
    k_softmax<<<NB, 128>>>(out_attn);
    // 9. res = res0@fc2 + b + x
    k_final<<<NB / 8, 128>>>(fc2_w, fc2_b, out_res);
}